// round 5
// baseline (speedup 1.0000x reference)
#include <cuda_runtime.h>
#include <math.h>

#define BB 16384
#define CC 8192
#define RPB 256              // rows per histogram block
#define NBLK (BB / RPB)      // 64

// ---------------- device scratch (no runtime allocation) ----------------
__device__ int   d_first[CC];          // first occurrence row per label (BB if absent)
__device__ int   d_cnt[CC];            // count per label
__device__ int   d_hist[NBLK * CC];    // per-row-block label histograms (raw counts)
__device__ int   d_start[BB];          // exclusive scan of group sizes (keyed by first-occ row)
__device__ int   d_lab[BB];            // normalized int32 labels
__device__ int   d_flagblk[32];        // per-block "odd word nonzero" flags
__device__ float d_loss[BB];           // per-row loss
__device__ unsigned int d_ticket;      // last-block election for loss reduction

// ---------------- setup: init first/cnt + label-width detection ----------------
__global__ void k_setup(const int* __restrict__ words) {
    int i = blockIdx.x * 256 + threadIdx.x;      // 0..8191
    d_first[i] = BB;
    d_cnt[i] = 0;
    int odd = (words[2 * i + 1] != 0);
    int any = __syncthreads_or(odd);
    if (threadIdx.x == 0) d_flagblk[blockIdx.x] = any;
    if (i == 0) d_ticket = 0;
}

// ---------------- convert + count (shared-memory histogram) ----------------
__global__ void __launch_bounds__(256) k_count(const void* __restrict__ labels) {
    __shared__ unsigned int sh[CC];   // 32KB block histogram
    __shared__ int s_is64;
    const int t = threadIdx.x, b = blockIdx.x;

    if (t < 32) {
        int v = d_flagblk[t];
        unsigned m = __ballot_sync(0xffffffffu, v != 0);
        if (t == 0) s_is64 = (m == 0);           // no odd word nonzero -> int64
    }
#pragma unroll
    for (int k = t; k < CC; k += 256) sh[k] = 0u;
    __syncthreads();

    const int i = b * 256 + t;
    const int lab = s_is64 ? (int)((const long long*)labels)[i]
                           : ((const int*)labels)[i];
    d_lab[i] = lab;
    atomicMin(&d_first[lab], i);
    atomicAdd(&d_cnt[lab], 1);
    atomicAdd(&sh[lab], 1u);
    __syncthreads();

#pragma unroll
    for (int k = t; k < CC; k += 256) d_hist[b * CC + k] = (int)sh[k];
}

// ---------------- group-start scan (single block) ----------------
__global__ void __launch_bounds__(1024) k_mid() {
    __shared__ int sums[1024];
    const int t = threadIdx.x;
    const int base = t * 16;
    int local[16];
    int acc = 0;
#pragma unroll
    for (int k = 0; k < 16; k++) {
        int r = base + k;
        int lab = d_lab[r];
        int gv = (d_first[lab] == r) ? d_cnt[lab] : 0;
        local[k] = acc;
        acc += gv;
    }
    sums[t] = acc;
    __syncthreads();
    for (int off = 1; off < 1024; off <<= 1) {
        int v = (t >= off) ? sums[t - off] : 0;
        __syncthreads();
        sums[t] += v;
        __syncthreads();
    }
    int offset = (t == 0) ? 0 : sums[t - 1];
#pragma unroll
    for (int k = 0; k < 16; k++) d_start[base + k] = offset + local[k];
}

// ---------------- main fused streaming kernel ----------------
// One block per source row. Issues ALL 8 row loads first (MLP=8 per thread),
// computes the permutation destination while the loads are in flight, then
// patches/stores/reduces. Last block reduces the loss deterministically.
__global__ void __launch_bounds__(256, 3) k_main(const float* __restrict__ logits,
                                                 float* __restrict__ out,
                                                 long long osz) {
    const int row = blockIdx.x;
    const int t = threadIdx.x;
    const float4* __restrict__ src = (const float4*)(logits + (size_t)row * CC);

    // ---- front-batched row loads: 8 independent LDG.128 per thread ----
    float4 x[8];
#pragma unroll
    for (int k = 0; k < 8; k++) x[k] = __ldcs(src + k * 256 + t);

    // ---- destination computation (overlaps with loads in flight) ----
    const int lab = d_lab[row];
    __shared__ float red[8];
    __shared__ int sred[8];
    __shared__ int s_dst;
    {
        const int blk = row >> 8, off = row & 255;
        int labj = d_lab[blk * 256 + t];
        int c = (t < off && labj == lab) ? 1 : 0;          // rank within 256-row block
        if (t < blk) c += d_hist[t * CC + lab];            // earlier blocks
#pragma unroll
        for (int o = 16; o; o >>= 1) c += __shfl_xor_sync(0xffffffffu, c, o);
        if ((t & 31) == 0) sred[t >> 5] = c;
        __syncthreads();
        if (t == 0) {
            int r = sred[0] + sred[1] + sred[2] + sred[3]
                  + sred[4] + sred[5] + sred[6] + sred[7];
            s_dst = d_start[d_first[lab]] + r;
        }
        __syncthreads();
    }
    const int dst = s_dst;
    float4* __restrict__ o4 = (float4*)(out + (size_t)dst * CC);

    const int tgt4 = lab >> 2, tsub = lab & 3;
    const long long nbig = (long long)BB * CC;
    const bool do_store = (osz >= nbig);

    // ---- patch target logit ----
    float tval = 0.0f;
    bool have_t = false;
#pragma unroll
    for (int k = 0; k < 8; k++) {
        if (k * 256 + t == tgt4) {
            float vv = (tsub == 0) ? x[k].x : (tsub == 1) ? x[k].y
                     : (tsub == 2) ? x[k].z : x[k].w;
            float nv = (vv > 0.0f) ? (vv / 2.00001f - 0.2f) : (vv * 2.00001f - 0.2f);
            if (tsub == 0) x[k].x = nv; else if (tsub == 1) x[k].y = nv;
            else if (tsub == 2) x[k].z = nv; else x[k].w = nv;
            tval = nv; have_t = true;
        }
    }

    // ---- stores issue ASAP ----
    if (do_store) {
#pragma unroll
        for (int k = 0; k < 8; k++) __stcs(o4 + k * 256 + t, x[k]);
    }

    // ---- sum of exp ----
    float s0 = 0.0f, s1 = 0.0f;
#pragma unroll
    for (int k = 0; k < 8; k++) {
        s0 += __expf(x[k].x) + __expf(x[k].y);
        s1 += __expf(x[k].z) + __expf(x[k].w);
    }
    float ws = s0 + s1;
#pragma unroll
    for (int o = 16; o; o >>= 1) ws += __shfl_xor_sync(0xffffffffu, ws, o);
    if ((t & 31) == 0) red[t >> 5] = ws;
    __syncthreads();
    if (t < 32) {
        float v = (t < 8) ? red[t] : 0.0f;
#pragma unroll
        for (int o = 4; o; o >>= 1) v += __shfl_xor_sync(0xffffffffu, v, o);
        if (t == 0) red[0] = v;
    }
    __syncthreads();
    const float s = red[0];

    if (have_t) {
        d_loss[row] = __logf(s) - tval;
        __threadfence();                       // publish loss before ticket
    }
    if (t == 0 && osz >= nbig + BB) out[(size_t)nbig + dst] = (float)lab;

    // ---- last block performs the deterministic loss reduction ----
    __shared__ unsigned int s_last;
    __syncthreads();
    if (t == 0) s_last = atomicAdd(&d_ticket, 1u);
    __syncthreads();
    if (s_last == BB - 1) {
        __threadfence();
        __shared__ double sd[256];
        double a = 0.0;
        for (int i = t; i < BB; i += 256) a += (double)d_loss[i];
        sd[t] = a;
        __syncthreads();
        for (int o = 128; o; o >>= 1) {
            if (t < o) sd[t] += sd[t + o];
            __syncthreads();
        }
        if (t == 0) {
            float L = (float)(sd[0] / (double)BB);
            if (osz >= nbig + BB + 1)      out[(size_t)nbig + BB] = L;
            else if (osz == 1)             out[0] = L;
        }
    }
}

// ---------------- launch ----------------
extern "C" void kernel_launch(void* const* d_in, const int* in_sizes, int n_in,
                              void* d_out, int out_size) {
    const float* logits = (const float*)d_in[0];
    const void*  labels = d_in[1];
    float* out = (float*)d_out;
    long long osz = (long long)out_size;

    k_setup<<<32, 256>>>((const int*)labels);
    k_count<<<NBLK, RPB>>>(labels);
    k_mid<<<1, 1024>>>();
    k_main<<<BB, 256>>>(logits, out, osz);
}

// round 6
// speedup vs baseline: 1.0542x; 1.0542x over previous
#include <cuda_runtime.h>
#include <math.h>

#define BB 16384
#define CC 8192
#define RPB 256              // rows per histogram block
#define NBLK (BB / RPB)      // 64

// ---------------- device scratch (no runtime allocation) ----------------
__device__ int   d_first[CC];          // first occurrence row per label (BB if absent)
__device__ int   d_cnt[CC];            // count per label
__device__ int   d_hist[NBLK * CC];    // per-row-block label histograms (raw counts)
__device__ int   d_start[BB];          // exclusive scan of group sizes (keyed by first-occ row)
__device__ int   d_rank[BB];           // stable rank of row within its 256-row block (same label)
__device__ int   d_pp[BB];             // rank + same-label count in earlier blocks
__device__ int   d_lab[BB];            // normalized int32 labels
__device__ int   d_flagblk[32];        // per-block "odd word nonzero" flags
__device__ float d_loss[BB];           // per-row loss
__device__ unsigned int d_ticket;      // last-block election for loss reduction

// ---------------- setup: init first/cnt + label-width detection ----------------
__global__ void k_setup(const int* __restrict__ words) {
    int i = blockIdx.x * 256 + threadIdx.x;      // 0..8191
    d_first[i] = BB;
    d_cnt[i] = 0;
    int odd = (words[2 * i + 1] != 0);
    int any = __syncthreads_or(odd);
    if (threadIdx.x == 0) d_flagblk[blockIdx.x] = any;
    if (i == 0) d_ticket = 0;
}

// ---------------- convert + count + stable in-block rank ----------------
// Warp-ordered phases: each warp computes in-warp stable ranks via a shfl
// match mask, reads the running block histogram for its cross-warp base,
// then advances the histogram. After 8 phases the histogram is the full
// block histogram (written to d_hist) and every row has its stable rank.
__global__ void __launch_bounds__(256) k_count(const void* __restrict__ labels) {
    __shared__ int srun[CC];          // 32KB running block histogram
    __shared__ int s_is64;
    const int t = threadIdx.x, b = blockIdx.x;
    const int l = t & 31, w = t >> 5;

    if (t < 32) {
        int v = d_flagblk[t];
        unsigned m = __ballot_sync(0xffffffffu, v != 0);
        if (t == 0) s_is64 = (m == 0);           // no odd word nonzero -> int64
    }
#pragma unroll
    for (int k = t; k < CC; k += 256) srun[k] = 0;
    __syncthreads();

    const int i = b * 256 + t;
    const int lab = s_is64 ? (int)((const long long*)labels)[i]
                           : ((const int*)labels)[i];
    d_lab[i] = lab;
    atomicMin(&d_first[lab], i);
    atomicAdd(&d_cnt[lab], 1);

    // in-warp match mask
    unsigned eq = 0u;
#pragma unroll
    for (int j = 0; j < 32; j++) {
        int lj = __shfl_sync(0xffffffffu, lab, j);
        eq |= (unsigned)(lj == lab) << j;
    }
    const int before  = __popc(eq & ((1u << l) - 1u));   // same-label lanes before me
    const int total   = __popc(eq);                      // same-label lanes in warp
    const bool is_last = (31 - __clz(eq)) == l;          // I am the highest such lane

    // warp-ordered cross-warp accumulation
    int rank = 0;
    for (int ph = 0; ph < 8; ph++) {
        if (w == ph) {
            rank = srun[lab] + before;
            __syncwarp();
            if (is_last) atomicAdd(&srun[lab], total);
        }
        __syncthreads();
    }
    d_rank[i] = rank;

#pragma unroll
    for (int k = t; k < CC; k += 256) d_hist[b * CC + k] = srun[k];
}

// ---------------- mid: group-start scan (block 16) + cross-block prefix (0-15) ----------------
__global__ void __launch_bounds__(1024) k_mid() {
    const int t = threadIdx.x;
    if (blockIdx.x == 16) {
        __shared__ int sums[1024];
        const int base = t * 16;
        int local[16];
        int acc = 0;
#pragma unroll
        for (int k = 0; k < 16; k++) {
            int r = base + k;
            int lab = d_lab[r];
            int gv = (d_first[lab] == r) ? d_cnt[lab] : 0;
            local[k] = acc;
            acc += gv;
        }
        sums[t] = acc;
        __syncthreads();
        for (int off = 1; off < 1024; off <<= 1) {
            int v = (t >= off) ? sums[t - off] : 0;
            __syncthreads();
            sums[t] += v;
            __syncthreads();
        }
        int offset = (t == 0) ? 0 : sums[t - 1];
#pragma unroll
        for (int k = 0; k < 16; k++) d_start[base + k] = offset + local[k];
    } else {
        const int r = blockIdx.x * 1024 + t;
        const int lab = d_lab[r];
        const int blk = r >> 8;
        int s = d_rank[r];
        for (int b2 = 0; b2 < blk; b2++) s += d_hist[b2 * CC + lab];
        d_pp[r] = s;
    }
}

// ---------------- main streaming kernel (no pre-stream barriers) ----------------
__global__ void __launch_bounds__(256) k_main(const float* __restrict__ logits,
                                              float* __restrict__ out,
                                              long long osz) {
    const int row = blockIdx.x;
    const int t = threadIdx.x;
    const int lab = d_lab[row];
    const int dst = d_start[d_first[lab]] + d_pp[row];
    const float4* __restrict__ src = (const float4*)(logits + (size_t)row * CC);
    float4* __restrict__ o4 = (float4*)(out + (size_t)dst * CC);

    const int tgt4 = lab >> 2, tsub = lab & 3;
    const long long nbig = (long long)BB * CC;
    const bool do_store = (osz >= nbig);

    float s0 = 0.0f, s1 = 0.0f;
    float tval = 0.0f;
    bool have_t = false;

#pragma unroll
    for (int k = 0; k < 8; k++) {
        const int idx = k * 256 + t;
        float4 x = __ldcs(src + idx);
        if (idx == tgt4) {
            float vv = (tsub == 0) ? x.x : (tsub == 1) ? x.y : (tsub == 2) ? x.z : x.w;
            float nv = (vv > 0.0f) ? (vv / 2.00001f - 0.2f) : (vv * 2.00001f - 0.2f);
            if (tsub == 0) x.x = nv; else if (tsub == 1) x.y = nv;
            else if (tsub == 2) x.z = nv; else x.w = nv;
            tval = nv; have_t = true;
        }
        if (do_store) __stcs(o4 + idx, x);
        s0 += __expf(x.x) + __expf(x.y);
        s1 += __expf(x.z) + __expf(x.w);
    }

    // block float-sum reduction
    __shared__ float red[8];
    float ws = s0 + s1;
#pragma unroll
    for (int o = 16; o; o >>= 1) ws += __shfl_xor_sync(0xffffffffu, ws, o);
    if ((t & 31) == 0) red[t >> 5] = ws;
    __syncthreads();
    if (t < 32) {
        float v = (t < 8) ? red[t] : 0.0f;
#pragma unroll
        for (int o = 4; o; o >>= 1) v += __shfl_xor_sync(0xffffffffu, v, o);
        if (t == 0) red[0] = v;
    }
    __syncthreads();
    const float s = red[0];

    if (have_t) {
        d_loss[row] = __logf(s) - tval;
        __threadfence();                       // publish loss before ticket
    }
    if (t == 0 && osz >= nbig + BB) out[(size_t)nbig + dst] = (float)lab;

    // ---- last block performs the deterministic loss reduction ----
    __shared__ unsigned int s_last;
    __syncthreads();
    if (t == 0) s_last = atomicAdd(&d_ticket, 1u);
    __syncthreads();
    if (s_last == BB - 1) {
        __threadfence();
        __shared__ double sd[256];
        double a = 0.0;
        for (int i = t; i < BB; i += 256) a += (double)d_loss[i];
        sd[t] = a;
        __syncthreads();
        for (int o = 128; o; o >>= 1) {
            if (t < o) sd[t] += sd[t + o];
            __syncthreads();
        }
        if (t == 0) {
            float L = (float)(sd[0] / (double)BB);
            if (osz >= nbig + BB + 1)      out[(size_t)nbig + BB] = L;
            else if (osz == 1)             out[0] = L;
        }
    }
}

// ---------------- launch ----------------
extern "C" void kernel_launch(void* const* d_in, const int* in_sizes, int n_in,
                              void* d_out, int out_size) {
    const float* logits = (const float*)d_in[0];
    const void*  labels = d_in[1];
    float* out = (float*)d_out;
    long long osz = (long long)out_size;

    k_setup<<<32, 256>>>((const int*)labels);
    k_count<<<NBLK, RPB>>>(labels);
    k_mid<<<17, 1024>>>();
    k_main<<<BB, 256>>>(logits, out, osz);
}